// round 10
// baseline (speedup 1.0000x reference)
#include <cuda_runtime.h>

// Problem constants
#define BATCH   64
#define TLEN    8192
#define DECL    64
#define NWIN    (TLEN - DECL)      // 8128
#define CHUNKS  8
#define WPC     (NWIN / CHUNKS)    // 1016 windows per chunk = 127*8
#define TPB     128
#define WPT     8                  // 128*8 = 1024 >= 1016; only tid==127 fully invalid

// smem x tile: max local read index = 1016 + 71 = 1087
#define XTILE   1088
#define XTILEP  (XTILE + XTILE / 8)   // pad i -> i + i/8: stride-8 refill -> stride 9, conflict-free

// Cross-block combine scratch (zero-init; kernel restores zeros after use so
// every graph replay sees identical initial state).
__device__ unsigned long long g_best[BATCH]; // max over ~key
__device__ unsigned int       g_cnt[BATCH];

__device__ __forceinline__ int padi(int i) { return i + (i >> 3); }

union F2U { float2 f; unsigned long long u; };

// Packed dual FMA: d = a*b + d (per 32-bit lane). Only reachable via PTX.
__device__ __forceinline__ void ffma2(F2U& d, const F2U& a, const F2U& b) {
    asm("fma.rn.f32x2 %0, %1, %2, %0;" : "+l"(d.u) : "l"(a.u), "l"(b.u));
}

// min-blocks = 4 (actual residency is 512/148 = 3.46 blocks/SM), so ptxas gets
// a 128-register budget for deep LDS hoisting over the fully-unrolled body.
__global__ __launch_bounds__(TPB, 4)
void match_kernel(const float* __restrict__ X_in,
                  const float* __restrict__ X_out,
                  float* __restrict__ out)
{
    __shared__ float  xs[XTILEP];
    __shared__ float4 ys4[DECL / 2];           // (y_j, y_j, y_{j+1}, y_{j+1})
    __shared__ unsigned long long red[TPB / 32];
    __shared__ int lastFlag;

    const int c   = blockIdx.x;     // chunk
    const int b   = blockIdx.y;     // batch
    const int tid = threadIdx.x;

    const float* xb = X_in + (size_t)b * TLEN;
    const int base  = c * WPC;      // multiple of 8 -> float4-aligned

    // y first (overlaps with x tile LDGs): 32 threads build duplicated pairs.
    if (tid < DECL / 2) {
        float2 v = ((const float2*)(X_out + b * DECL))[tid];
        ys4[tid] = make_float4(v.x, v.x, v.y, v.y);
    }
    // Vectorized tile load: 272 float4 loads, ~2.1 per thread, high MLP.
    {
        const float4* xb4 = (const float4*)(xb + base);
        for (int i4 = tid; i4 < XTILE / 4; i4 += TPB) {
            int i = i4 * 4;
            if (base + i + 3 < TLEN) {
                float4 v = xb4[i4];
                xs[padi(i + 0)] = v.x;
                xs[padi(i + 1)] = v.y;
                xs[padi(i + 2)] = v.z;
                xs[padi(i + 3)] = v.w;
            } else {
                #pragma unroll
                for (int k = 0; k < 4; ++k) {
                    int g = base + i + k;
                    xs[padi(i + k)] = (g < TLEN) ? xb[g] : 0.0f;
                }
            }
        }
    }
    __syncthreads();

    const int l0 = tid * WPT;

    // Packed sliding ring: at step j, pr[(j+k)&3] = (x[l0+j+k], x[l0+j+k+4]).
    F2U pr[4];
    #pragma unroll
    for (int k = 0; k < 4; ++k) {
        pr[k].f.x = xs[padi(l0 + k)];
        pr[k].f.y = xs[padi(l0 + k + 4)];
    }

    F2U pacc[4];                    // pacc[k] = (acc_k, acc_{k+4})
    #pragma unroll
    for (int k = 0; k < 4; ++k) { pacc[k].f.x = 0.f; pacc[k].f.y = 0.f; }
    float sx2 = 0.f;                // sum x^2 for window w=0

    // Main loop: 2 j-steps per iteration; one LDS.128 per iteration for y,
    // software-pipelined one iteration ahead. Ring refills prefetched at the
    // top of each iteration. Fully unrolled; with the 128-reg budget ptxas
    // can hoist loads across iteration boundaries.
    float4 yq = ys4[0];
    #pragma unroll
    for (int j2 = 0; j2 < DECL / 2; ++j2) {
        const int j = 2 * j2;
        float4 yqn;
        if (j2 + 1 < DECL / 2) yqn = ys4[j2 + 1]; // prefetch next y quad
        float nh0 = xs[padi(l0 + j + 8)];         // prefetch both refills
        float nh1 = xs[padi(l0 + j + 9)];

        // step j (even)
        {
            F2U ya; ya.f.x = yq.x; ya.f.y = yq.y;
            ffma2(pacc[0], pr[(j + 0) & 3], ya);
            ffma2(pacc[1], pr[(j + 1) & 3], ya);
            ffma2(pacc[2], pr[(j + 2) & 3], ya);
            ffma2(pacc[3], pr[(j + 3) & 3], ya);
            float vlo = pr[j & 3].f.x;            // leaving element x[l0+j]
            sx2 = fmaf(vlo, vlo, sx2);
            pr[j & 3].f.x = pr[j & 3].f.y;        // pair shift
            pr[j & 3].f.y = nh0;
        }
        // step j+1 (odd)
        {
            F2U yb; yb.f.x = yq.z; yb.f.y = yq.w;
            ffma2(pacc[0], pr[(j + 1) & 3], yb);
            ffma2(pacc[1], pr[(j + 2) & 3], yb);
            ffma2(pacc[2], pr[(j + 3) & 3], yb);
            ffma2(pacc[3], pr[(j + 4) & 3], yb);
            float vlo = pr[(j + 1) & 3].f.x;      // leaving element x[l0+j+1]
            sx2 = fmaf(vlo, vlo, sx2);
            pr[(j + 1) & 3].f.x = pr[(j + 1) & 3].f.y;
            pr[(j + 1) & 3].f.y = nh1;
        }
        yq = yqn;
    }
    // After loop: pr[k] = (x[l0+64+k], x[l0+68+k]), k=0..3.

    float acc[8];
    #pragma unroll
    for (int k = 0; k < 4; ++k) { acc[k] = pacc[k].f.x; acc[k + 4] = pacc[k].f.y; }

    float score[8];
    score[0] = fmaf(-2.0f, acc[0], sx2);
    float s = sx2;
    #pragma unroll
    for (int w = 1; w < 8; ++w) {
        float xin  = (w <= 4) ? pr[w - 1].f.x : pr[w - 5].f.y;  // x[l0+w+63]
        float xout = xs[padi(l0 + w - 1)];                       // x[l0+w-1]
        s = fmaf(xin, xin, s);
        s = fmaf(-xout, xout, s);
        score[w] = fmaf(-2.0f, acc[w], s);
    }

    // Thread-local tournament argmin (strict < keeps first index on ties;
    // indices ascend within a thread, so tie-break = smallest index).
    float bs = score[0];
    int   bw = 0;
    #pragma unroll
    for (int w = 1; w < 8; ++w) {
        bool better = score[w] < bs;
        bs = better ? score[w] : bs;
        bw = better ? w : bw;
    }
    if (tid == TPB - 1) bs = __int_as_float(0x7F800000); // only thread with invalid windows

    // Single monotonic pack: max over ~key == min score, tie -> smaller idx.
    unsigned long long bestik;
    {
        unsigned gidx = (unsigned)(base + l0 + bw);
        unsigned u = __float_as_uint(bs);
        unsigned m = u ^ ((unsigned)((int)u >> 31) | 0x80000000u);
        bestik = ~(((unsigned long long)m << 32) | gidx);
    }

    // Warp reduce (max over ~key)
    #pragma unroll
    for (int o = 16; o; o >>= 1) {
        unsigned long long v = __shfl_down_sync(0xFFFFFFFFu, bestik, o);
        bestik = bestik > v ? bestik : v;
    }
    if ((tid & 31) == 0) red[tid >> 5] = bestik;
    __syncthreads();

    if (tid == 0) {
        unsigned long long k = red[0];
        #pragma unroll
        for (int i = 1; i < TPB / 32; ++i) k = k > red[i] ? k : red[i];
        atomicMax(&g_best[b], k);
        __threadfence();
        unsigned prev = atomicAdd(&g_cnt[b], 1u);
        lastFlag = (prev == CHUNKS - 1) ? 1 : 0;
    }
    __syncthreads();

    // Last block for this batch gathers output and restores scratch.
    // After the fence+counter handshake, prior atomicMax results are visible;
    // a volatile read suffices (no ATOMG round-trip).
    if (lastFlag) {
        unsigned long long k = *(volatile unsigned long long*)&g_best[b];
        int start = (int)((~k) & 0xFFFFFFFFull);
        if (tid < DECL) out[b * DECL + tid] = xb[start + tid];
        __syncthreads();
        if (tid == 0) { g_best[b] = 0ULL; g_cnt[b] = 0u; }
    }
}

extern "C" void kernel_launch(void* const* d_in, const int* in_sizes, int n_in,
                              void* d_out, int out_size)
{
    // inputs: 0=feats_in (unused), 1=X_in, 2=feats_out (unused), 3=X_out
    const float* X_in  = (const float*)d_in[1];
    const float* X_out = (const float*)d_in[3];
    float* out = (float*)d_out;

    dim3 grid(CHUNKS, BATCH);
    match_kernel<<<grid, TPB>>>(X_in, X_out, out);
}

// round 11
// speedup vs baseline: 1.0239x; 1.0239x over previous
#include <cuda_runtime.h>

// Problem constants
#define BATCH   64
#define TLEN    8192
#define DECL    64
#define NWIN    (TLEN - DECL)      // 8128
#define CHUNKS  16
#define WPC     (NWIN / CHUNKS)    // 508 windows per chunk (exact: 16*508 = 8128)
#define TPB     64
#define WPT     8                  // 64*8 = 512 >= 508; tid 63 has 4 invalid windows

// smem x tile: max local read index = 504 + 71 = 575
#define XTILE   576
#define XTILEP  (XTILE + XTILE / 8)   // pad i -> i + i/8: stride-8 refill -> stride 9, conflict-free

// Cross-block combine scratch (zero-init; kernel restores zeros after use so
// every graph replay sees identical initial state).
__device__ unsigned long long g_best[BATCH]; // max over ~key
__device__ unsigned int       g_cnt[BATCH];

__device__ __forceinline__ int padi(int i) { return i + (i >> 3); }

union F2U { float2 f; unsigned long long u; };

// Packed dual FMA: d = a*b + d (per 32-bit lane). Only reachable via PTX.
__device__ __forceinline__ void ffma2(F2U& d, const F2U& a, const F2U& b) {
    asm("fma.rn.f32x2 %0, %1, %2, %0;" : "+l"(d.u) : "l"(a.u), "l"(b.u));
}

__global__ __launch_bounds__(TPB, 8)
void match_kernel(const float* __restrict__ X_in,
                  const float* __restrict__ X_out,
                  float* __restrict__ out)
{
    __shared__ float  xs[XTILEP];
    __shared__ float4 ys4[DECL / 2];           // (y_j, y_j, y_{j+1}, y_{j+1})
    __shared__ unsigned long long red[TPB / 32];
    __shared__ int lastFlag;

    const int c   = blockIdx.x;     // chunk
    const int b   = blockIdx.y;     // batch
    const int tid = threadIdx.x;

    const float* xb = X_in + (size_t)b * TLEN;
    const int base  = c * WPC;      // 508*c, multiple of 4 -> float4-aligned

    // y first (overlaps with x tile LDGs): 32 threads build duplicated pairs.
    if (tid < DECL / 2) {
        float2 v = ((const float2*)(X_out + b * DECL))[tid];
        ys4[tid] = make_float4(v.x, v.x, v.y, v.y);
    }
    // Vectorized tile load: 144 float4 loads, ~2.25 per thread, high MLP.
    {
        const float4* xb4 = (const float4*)(xb + base);
        #pragma unroll
        for (int i4 = tid; i4 < XTILE / 4; i4 += TPB) {
            int i = i4 * 4;
            if (base + i + 3 < TLEN) {
                float4 v = xb4[i4];
                xs[padi(i + 0)] = v.x;
                xs[padi(i + 1)] = v.y;
                xs[padi(i + 2)] = v.z;
                xs[padi(i + 3)] = v.w;
            } else {
                #pragma unroll
                for (int k = 0; k < 4; ++k) {
                    int g = base + i + k;
                    xs[padi(i + k)] = (g < TLEN) ? xb[g] : 0.0f;
                }
            }
        }
    }
    __syncthreads();

    const int l0 = tid * WPT;

    // Packed sliding ring: at step j, pr[(j+k)&3] = (x[l0+j+k], x[l0+j+k+4]).
    F2U pr[4];
    #pragma unroll
    for (int k = 0; k < 4; ++k) {
        pr[k].f.x = xs[padi(l0 + k)];
        pr[k].f.y = xs[padi(l0 + k + 4)];
    }

    F2U pacc[4];                    // pacc[k] = (acc_k, acc_{k+4})
    #pragma unroll
    for (int k = 0; k < 4; ++k) { pacc[k].f.x = 0.f; pacc[k].f.y = 0.f; }
    float sx2 = 0.f;                // sum x^2 for window w=0

    // Main loop: 2 j-steps per iteration; one LDS.128 per iteration for y,
    // pipelined one iteration ahead; both ring refills prefetched up front.
    float4 yq = ys4[0];
    #pragma unroll
    for (int j2 = 0; j2 < DECL / 2; ++j2) {
        const int j = 2 * j2;
        float4 yqn;
        if (j2 + 1 < DECL / 2) yqn = ys4[j2 + 1]; // prefetch next y quad
        float nh0 = xs[padi(l0 + j + 8)];         // prefetch both refills
        float nh1 = xs[padi(l0 + j + 9)];

        // step j (even)
        {
            F2U ya; ya.f.x = yq.x; ya.f.y = yq.y;
            ffma2(pacc[0], pr[(j + 0) & 3], ya);
            ffma2(pacc[1], pr[(j + 1) & 3], ya);
            ffma2(pacc[2], pr[(j + 2) & 3], ya);
            ffma2(pacc[3], pr[(j + 3) & 3], ya);
            float vlo = pr[j & 3].f.x;            // leaving element x[l0+j]
            sx2 = fmaf(vlo, vlo, sx2);
            pr[j & 3].f.x = pr[j & 3].f.y;        // pair shift
            pr[j & 3].f.y = nh0;
        }
        // step j+1 (odd)
        {
            F2U yb; yb.f.x = yq.z; yb.f.y = yq.w;
            ffma2(pacc[0], pr[(j + 1) & 3], yb);
            ffma2(pacc[1], pr[(j + 2) & 3], yb);
            ffma2(pacc[2], pr[(j + 3) & 3], yb);
            ffma2(pacc[3], pr[(j + 4) & 3], yb);
            float vlo = pr[(j + 1) & 3].f.x;      // leaving element x[l0+j+1]
            sx2 = fmaf(vlo, vlo, sx2);
            pr[(j + 1) & 3].f.x = pr[(j + 1) & 3].f.y;
            pr[(j + 1) & 3].f.y = nh1;
        }
        yq = yqn;
    }
    // After loop: pr[k] = (x[l0+64+k], x[l0+68+k]), k=0..3.

    float acc[8];
    #pragma unroll
    for (int k = 0; k < 4; ++k) { acc[k] = pacc[k].f.x; acc[k + 4] = pacc[k].f.y; }

    float score[8];
    score[0] = fmaf(-2.0f, acc[0], sx2);
    float s = sx2;
    #pragma unroll
    for (int w = 1; w < 8; ++w) {
        float xin  = (w <= 4) ? pr[w - 1].f.x : pr[w - 5].f.y;  // x[l0+w+63]
        float xout = xs[padi(l0 + w - 1)];                       // x[l0+w-1]
        s = fmaf(xin, xin, s);
        s = fmaf(-xout, xout, s);
        score[w] = fmaf(-2.0f, acc[w], s);
    }

    // Only tid 63's windows 4..7 (local 508..511) are invalid.
    if (tid == TPB - 1) {
        score[4] = __int_as_float(0x7F800000);
        score[5] = __int_as_float(0x7F800000);
        score[6] = __int_as_float(0x7F800000);
        score[7] = __int_as_float(0x7F800000);
    }

    // Thread-local tournament argmin (strict < keeps first index on ties;
    // indices ascend within a thread, so tie-break = smallest index).
    float bs = score[0];
    int   bw = 0;
    #pragma unroll
    for (int w = 1; w < 8; ++w) {
        bool better = score[w] < bs;
        bs = better ? score[w] : bs;
        bw = better ? w : bw;
    }

    // Single monotonic pack: max over ~key == min score, tie -> smaller idx.
    unsigned long long bestik;
    {
        unsigned gidx = (unsigned)(base + l0 + bw);
        unsigned u = __float_as_uint(bs);
        unsigned m = u ^ ((unsigned)((int)u >> 31) | 0x80000000u);
        bestik = ~(((unsigned long long)m << 32) | gidx);
    }

    // Warp reduce (max over ~key)
    #pragma unroll
    for (int o = 16; o; o >>= 1) {
        unsigned long long v = __shfl_down_sync(0xFFFFFFFFu, bestik, o);
        bestik = bestik > v ? bestik : v;
    }
    if ((tid & 31) == 0) red[tid >> 5] = bestik;
    __syncthreads();

    if (tid == 0) {
        unsigned long long k = red[0];
        unsigned long long k1 = red[1];
        k = k > k1 ? k : k1;
        atomicMax(&g_best[b], k);
        __threadfence();
        unsigned prev = atomicAdd(&g_cnt[b], 1u);
        lastFlag = (prev == CHUNKS - 1) ? 1 : 0;
    }
    __syncthreads();

    // Last block for this batch gathers output and restores scratch.
    // After the fence+counter handshake, prior atomicMax results are visible;
    // a volatile read suffices (no ATOMG round-trip).
    if (lastFlag) {
        unsigned long long k = *(volatile unsigned long long*)&g_best[b];
        int start = (int)((~k) & 0xFFFFFFFFull);
        if (tid < DECL) out[b * DECL + tid] = xb[start + tid];
        __syncthreads();
        if (tid == 0) { g_best[b] = 0ULL; g_cnt[b] = 0u; }
    }
}

extern "C" void kernel_launch(void* const* d_in, const int* in_sizes, int n_in,
                              void* d_out, int out_size)
{
    // inputs: 0=feats_in (unused), 1=X_in, 2=feats_out (unused), 3=X_out
    const float* X_in  = (const float*)d_in[1];
    const float* X_out = (const float*)d_in[3];
    float* out = (float*)d_out;

    dim3 grid(CHUNKS, BATCH);
    match_kernel<<<grid, TPB>>>(X_in, X_out, out);
}